// round 2
// baseline (speedup 1.0000x reference)
#include <cuda_runtime.h>
#include <math.h>

// Problem constants
#define BB 2
#define TT 2048
#define CC 1024
#define HH 16
#define HD 64
// M rows for projections = B*T
#define MROWS (BB*TT)

// Scratch (allocation-free rule: __device__ globals)
__device__ float g_q[BB*HH*TT*HD];
__device__ float g_k[BB*HH*TT*HD];
__device__ float g_v[BB*HH*TT*HD];
__device__ float g_ao[BB*HH*TT*HD];

// ---------------------------------------------------------------------------
// 128x128x8 tiled fp32 GEMM: Y[M,N] = X[M,K] @ W[K,N] + bias[N]
// IN_PERM : X is read from [B,H,T,HD] layout as logical [B*T, H*HD]
// OUT_PERM: Y is written to [B,H,T,HD] layout from logical [B*T, H*HD]
// ---------------------------------------------------------------------------
template<bool IN_PERM, bool OUT_PERM>
__global__ __launch_bounds__(256)
void gemm128(const float* __restrict__ X, const float* __restrict__ W,
             const float* __restrict__ bias, float* __restrict__ Y,
             int M, int N, int K)
{
    __shared__ float As[8][128];   // As[k][m] (transposed X tile)
    __shared__ float Bs[8][128];   // Bs[k][n]

    const int tid = threadIdx.x;
    const int bm = blockIdx.y * 128;
    const int bn = blockIdx.x * 128;

    // X tile load mapping: 128 rows x 8 cols = 1024 floats = 256 float4
    const int lxr = tid >> 1;           // row 0..127
    const int lxc = (tid & 1) * 4;      // col 0 or 4
    // W tile load mapping: 8 rows x 128 cols
    const int lwr = tid >> 5;           // row 0..7
    const int lwc = (tid & 31) * 4;     // col 0..124

    const int ty = tid >> 4;            // 0..15 (rows)
    const int tx = tid & 15;            // 0..15 (cols)

    float acc[8][8];
#pragma unroll
    for (int i = 0; i < 8; i++)
#pragma unroll
        for (int j = 0; j < 8; j++) acc[i][j] = 0.f;

    for (int k0 = 0; k0 < K; k0 += 8) {
        // ---- load X tile (transposed into As) ----
        const int xm = bm + lxr;
        const int xk = k0 + lxc;
        const float* xp;
        if (IN_PERM) {
            // logical X[m][k] = src[((b*H + h)*T + t)*HD + d]
            const int b = xm >> 11;         // /T (T=2048)
            const int t = xm & (TT - 1);
            const int h = xk >> 6;          // /HD
            const int d = xk & (HD - 1);
            xp = X + ((((size_t)b*HH + h)*TT + t)*HD + d);
        } else {
            xp = X + (size_t)xm * K + xk;
        }
        float4 xv = *(const float4*)xp;
        As[lxc + 0][lxr] = xv.x;
        As[lxc + 1][lxr] = xv.y;
        As[lxc + 2][lxr] = xv.z;
        As[lxc + 3][lxr] = xv.w;

        // ---- load W tile ----
        float4 wv = *(const float4*)(W + (size_t)(k0 + lwr) * N + bn + lwc);
        *(float4*)&Bs[lwr][lwc] = wv;

        __syncthreads();

        // ---- compute ----
#pragma unroll
        for (int kk = 0; kk < 8; kk++) {
            float af[8], bf[8];
            *(float4*)&af[0] = *(const float4*)&As[kk][ty * 8];
            *(float4*)&af[4] = *(const float4*)&As[kk][ty * 8 + 4];
            *(float4*)&bf[0] = *(const float4*)&Bs[kk][tx * 8];
            *(float4*)&bf[4] = *(const float4*)&Bs[kk][tx * 8 + 4];
#pragma unroll
            for (int i = 0; i < 8; i++)
#pragma unroll
                for (int j = 0; j < 8; j++)
                    acc[i][j] += af[i] * bf[j];
        }
        __syncthreads();
    }

    // ---- epilogue: bias + store ----
#pragma unroll
    for (int i = 0; i < 8; i++) {
        const int m = bm + ty * 8 + i;
        const int b = m >> 11;
        const int t = m & (TT - 1);
#pragma unroll
        for (int j = 0; j < 8; j += 4) {
            const int n = bn + tx * 8 + j;
            float4 r;
            r.x = acc[i][j + 0] + __ldg(bias + n + 0);
            r.y = acc[i][j + 1] + __ldg(bias + n + 1);
            r.z = acc[i][j + 2] + __ldg(bias + n + 2);
            r.w = acc[i][j + 3] + __ldg(bias + n + 3);
            float* yp;
            if (OUT_PERM) {
                const int h = n >> 6;
                const int d = n & (HD - 1);
                yp = Y + ((((size_t)b*HH + h)*TT + t)*HD + d);
            } else {
                yp = Y + (size_t)m * N + n;
            }
            *(float4*)yp = r;
        }
    }
}

// ---------------------------------------------------------------------------
// Flash-style causal attention, fp32.
// One thread per query row; 128 q rows per block; 64-key K/V smem tiles.
// grid = (T/128, H, B), block = 128
// ---------------------------------------------------------------------------
__global__ __launch_bounds__(128)
void flash(const float* __restrict__ Q, const float* __restrict__ Kg,
           const float* __restrict__ Vg, float* __restrict__ O)
{
    __shared__ float Ks[64][HD];
    __shared__ float Vs[64][HD];

    const int tid = threadIdx.x;
    const int qt = blockIdx.x;
    const int h  = blockIdx.y;
    const int b  = blockIdx.z;
    const int qi = qt * 128 + tid;              // global query row in [0,T)

    const size_t head_base = (((size_t)b * HH + h) * TT) * HD;
    const float* qp = Q + head_base + (size_t)qi * HD;

    float qreg[HD];
#pragma unroll
    for (int d4 = 0; d4 < HD / 4; d4++)
        *(float4*)&qreg[d4 * 4] = *(const float4*)(qp + d4 * 4);

    float oacc[HD];
#pragma unroll
    for (int d = 0; d < HD; d++) oacc[d] = 0.f;

    float mmax = -1e30f;
    float lsum = 0.f;
    const float scale = 0.125f;                 // 1/sqrt(64)

    const float* kbase = Kg + head_base;
    const float* vbase = Vg + head_base;
    const int kv_end = qt * 128 + 128;          // causal: keys < kv_end matter

    for (int kv0 = 0; kv0 < kv_end; kv0 += 64) {
        __syncthreads();
        // load K/V tiles: 64x64 floats each = 1024 float4 per tile.
        // 128 threads x 8 iterations = 1024 float4 (FIX: was 4 iterations,
        // which left rows 32..63 of Ks/Vs unwritten)
#pragma unroll
        for (int i = 0; i < 8; i++) {
            const int idx = i * 128 + tid;      // float4 index 0..1023
            const int r = idx >> 4;             // row 0..63
            const int c = (idx & 15) * 4;       // col 0..60
            *(float4*)&Ks[r][c] = *(const float4*)(kbase + (size_t)(kv0 + r) * HD + c);
            *(float4*)&Vs[r][c] = *(const float4*)(vbase + (size_t)(kv0 + r) * HD + c);
        }
        __syncthreads();

#pragma unroll 1
        for (int c0 = 0; c0 < 64; c0 += 16) {
            if (kv0 + c0 > qi) continue;        // fully masked chunk for this row

            float s[16];
#pragma unroll
            for (int cc = 0; cc < 16; cc++) {
                const int kk = c0 + cc;
                float a = 0.f;
#pragma unroll
                for (int d4 = 0; d4 < HD / 4; d4++) {
                    const float4 kv4 = *(const float4*)&Ks[kk][d4 * 4];
                    a += qreg[d4*4+0] * kv4.x;
                    a += qreg[d4*4+1] * kv4.y;
                    a += qreg[d4*4+2] * kv4.z;
                    a += qreg[d4*4+3] * kv4.w;
                }
                s[cc] = (kv0 + kk > qi) ? -1e30f : a * scale;
            }

            float mt = mmax;
#pragma unroll
            for (int cc = 0; cc < 16; cc++) mt = fmaxf(mt, s[cc]);

            const float alpha = __expf(mmax - mt);
            lsum *= alpha;
#pragma unroll
            for (int d = 0; d < HD; d++) oacc[d] *= alpha;

#pragma unroll
            for (int cc = 0; cc < 16; cc++) {
                const float p = (kv0 + c0 + cc > qi) ? 0.f : __expf(s[cc] - mt);
                lsum += p;
#pragma unroll
                for (int d4 = 0; d4 < HD / 4; d4++) {
                    const float4 v4 = *(const float4*)&Vs[c0 + cc][d4 * 4];
                    oacc[d4*4+0] += p * v4.x;
                    oacc[d4*4+1] += p * v4.y;
                    oacc[d4*4+2] += p * v4.z;
                    oacc[d4*4+3] += p * v4.w;
                }
            }
            mmax = mt;
        }
    }

    const float inv = 1.f / lsum;
    float* op = O + head_base + (size_t)qi * HD;
#pragma unroll
    for (int d4 = 0; d4 < HD / 4; d4++) {
        float4 r;
        r.x = oacc[d4*4+0] * inv;
        r.y = oacc[d4*4+1] * inv;
        r.z = oacc[d4*4+2] * inv;
        r.w = oacc[d4*4+3] * inv;
        *(float4*)(op + d4 * 4) = r;
    }
}

// ---------------------------------------------------------------------------
extern "C" void kernel_launch(void* const* d_in, const int* in_sizes, int n_in,
                              void* d_out, int out_size)
{
    const float* x  = (const float*)d_in[0];
    const float* Wq = (const float*)d_in[1];
    const float* bq = (const float*)d_in[2];
    const float* Wk = (const float*)d_in[3];
    const float* bk = (const float*)d_in[4];
    const float* Wv = (const float*)d_in[5];
    const float* bv = (const float*)d_in[6];
    const float* Wo = (const float*)d_in[7];
    const float* bo = (const float*)d_in[8];
    float* out = (float*)d_out;

    float *q, *k, *v, *ao;
    cudaGetSymbolAddress((void**)&q,  g_q);
    cudaGetSymbolAddress((void**)&k,  g_k);
    cudaGetSymbolAddress((void**)&v,  g_v);
    cudaGetSymbolAddress((void**)&ao, g_ao);

    dim3 gemm_grid(CC / 128, MROWS / 128);   // (8, 32)
    dim3 gemm_blk(256);

    // QKV projections (write directly into [B,H,T,HD])
    gemm128<false, true><<<gemm_grid, gemm_blk>>>(x, Wq, bq, q, MROWS, CC, CC);
    gemm128<false, true><<<gemm_grid, gemm_blk>>>(x, Wk, bk, k, MROWS, CC, CC);
    gemm128<false, true><<<gemm_grid, gemm_blk>>>(x, Wv, bv, v, MROWS, CC, CC);

    // Causal attention
    dim3 att_grid(TT / 128, HH, BB);         // (16, 16, 2)
    flash<<<att_grid, 128>>>(q, k, v, ao);

    // Output projection (gather from [B,H,T,HD], write [B,T,C])
    gemm128<true, false><<<gemm_grid, gemm_blk>>>(ao, Wo, bo, out, MROWS, CC, CC);
}

// round 3
// speedup vs baseline: 1.2040x; 1.2040x over previous
#include <cuda_runtime.h>
#include <math.h>

// Problem constants
#define BB 2
#define TT 2048
#define CC 1024
#define HH 16
#define HD 64
#define MROWS (BB*TT)

// Scratch (allocation-free rule: __device__ globals)
__device__ float g_q[BB*HH*TT*HD];
__device__ float g_k[BB*HH*TT*HD];
__device__ float g_v[BB*HH*TT*HD];
__device__ float g_ao[BB*HH*TT*HD];

// ---------------------------------------------------------------------------
// 128x128x8 tiled fp32 GEMM: Y[M,N] = X[M,K] @ W[K,N] + bias[N]
// (unchanged from round 2 — already at fp32 FFMA roofline)
// ---------------------------------------------------------------------------
template<bool IN_PERM, bool OUT_PERM>
__global__ __launch_bounds__(256)
void gemm128(const float* __restrict__ X, const float* __restrict__ W,
             const float* __restrict__ bias, float* __restrict__ Y,
             int M, int N, int K)
{
    __shared__ float As[8][128];
    __shared__ float Bs[8][128];

    const int tid = threadIdx.x;
    const int bm = blockIdx.y * 128;
    const int bn = blockIdx.x * 128;

    const int lxr = tid >> 1;
    const int lxc = (tid & 1) * 4;
    const int lwr = tid >> 5;
    const int lwc = (tid & 31) * 4;

    const int ty = tid >> 4;
    const int tx = tid & 15;

    float acc[8][8];
#pragma unroll
    for (int i = 0; i < 8; i++)
#pragma unroll
        for (int j = 0; j < 8; j++) acc[i][j] = 0.f;

    for (int k0 = 0; k0 < K; k0 += 8) {
        const int xm = bm + lxr;
        const int xk = k0 + lxc;
        const float* xp;
        if (IN_PERM) {
            const int b = xm >> 11;
            const int t = xm & (TT - 1);
            const int h = xk >> 6;
            const int d = xk & (HD - 1);
            xp = X + ((((size_t)b*HH + h)*TT + t)*HD + d);
        } else {
            xp = X + (size_t)xm * K + xk;
        }
        float4 xv = *(const float4*)xp;
        As[lxc + 0][lxr] = xv.x;
        As[lxc + 1][lxr] = xv.y;
        As[lxc + 2][lxr] = xv.z;
        As[lxc + 3][lxr] = xv.w;

        float4 wv = *(const float4*)(W + (size_t)(k0 + lwr) * N + bn + lwc);
        *(float4*)&Bs[lwr][lwc] = wv;

        __syncthreads();

#pragma unroll
        for (int kk = 0; kk < 8; kk++) {
            float af[8], bf[8];
            *(float4*)&af[0] = *(const float4*)&As[kk][ty * 8];
            *(float4*)&af[4] = *(const float4*)&As[kk][ty * 8 + 4];
            *(float4*)&bf[0] = *(const float4*)&Bs[kk][tx * 8];
            *(float4*)&bf[4] = *(const float4*)&Bs[kk][tx * 8 + 4];
#pragma unroll
            for (int i = 0; i < 8; i++)
#pragma unroll
                for (int j = 0; j < 8; j++)
                    acc[i][j] += af[i] * bf[j];
        }
        __syncthreads();
    }

#pragma unroll
    for (int i = 0; i < 8; i++) {
        const int m = bm + ty * 8 + i;
        const int b = m >> 11;
        const int t = m & (TT - 1);
#pragma unroll
        for (int j = 0; j < 8; j += 4) {
            const int n = bn + tx * 8 + j;
            float4 r;
            r.x = acc[i][j + 0] + __ldg(bias + n + 0);
            r.y = acc[i][j + 1] + __ldg(bias + n + 1);
            r.z = acc[i][j + 2] + __ldg(bias + n + 2);
            r.w = acc[i][j + 3] + __ldg(bias + n + 3);
            float* yp;
            if (OUT_PERM) {
                const int h = n >> 6;
                const int d = n & (HD - 1);
                yp = Y + ((((size_t)b*HH + h)*TT + t)*HD + d);
            } else {
                yp = Y + (size_t)m * N + n;
            }
            *(float4*)yp = r;
        }
    }
}

// ---------------------------------------------------------------------------
// Block-tiled flash attention (fp32), GEMM-style register blocking.
// Block: 256 threads = 16(ty) x 16(tx). Q tile: 128 rows. KV tile: 64 keys.
// Each thread: 8 q-rows (ty*8+i) x 4 cols.
//   S phase: cols = 4 keys (tx*4+j)
//   PV phase: cols = 4 head-dims (tx*4+j)
// grid = (T/128, H, B)
// ---------------------------------------------------------------------------
#define FBM 128
#define FBN 64
#define KSL 68            // Ks row stride (floats), 16B-aligned rows
#define PSL 68            // Ps row stride

// dynamic smem layout (floats):
//   Qs [64][128]     (transposed, pre-scaled)      8192
//   Ks [64][KSL]     (transposed)                  4352
//   Vs [64][64]                                    4096
//   Ps [128][PSL]                                  8704
#define FLASH_SMEM_FLOATS (64*FBM + 64*KSL + 64*64 + FBM*PSL)

__global__ __launch_bounds__(256)
void flash2(const float* __restrict__ Q, const float* __restrict__ Kg,
            const float* __restrict__ Vg, float* __restrict__ O)
{
    extern __shared__ float sm[];
    float* Qs = sm;                       // [64][128]
    float* Ks = Qs + 64 * FBM;            // [64][KSL]
    float* Vs = Ks + 64 * KSL;            // [64][64]
    float* Ps = Vs + 64 * 64;             // [128][PSL]

    const int tid = threadIdx.x;
    const int ty = tid >> 4;              // 0..15
    const int tx = tid & 15;              // 0..15
    const int qt = blockIdx.x;
    const int h  = blockIdx.y;
    const int b  = blockIdx.z;

    const size_t head_base = (((size_t)b * HH + h) * TT) * HD;
    const float scale = 0.125f;           // 1/sqrt(64)

    // ---- load Q tile transposed + pre-scaled: Qs[d][m] ----
    {
        const int m  = tid & 127;                 // row within tile
        const int d0 = (tid >> 7) * 32;           // 0 or 32
        const float* qp = Q + head_base + (size_t)(qt * FBM + m) * HD + d0;
#pragma unroll
        for (int i = 0; i < 8; i++) {
            float4 v4 = *(const float4*)(qp + i * 4);
            Qs[(d0 + i*4 + 0) * FBM + m] = v4.x * scale;
            Qs[(d0 + i*4 + 1) * FBM + m] = v4.y * scale;
            Qs[(d0 + i*4 + 2) * FBM + m] = v4.z * scale;
            Qs[(d0 + i*4 + 3) * FBM + m] = v4.w * scale;
        }
    }

    float mrow[8], lrow[8], oacc[8][4];
#pragma unroll
    for (int i = 0; i < 8; i++) {
        mrow[i] = -1e30f;
        lrow[i] = 0.f;
#pragma unroll
        for (int j = 0; j < 4; j++) oacc[i][j] = 0.f;
    }

    const float* kbase = Kg + head_base;
    const float* vbase = Vg + head_base;
    const int ntiles = (qt + 1) * 2;

    for (int tile = 0; tile < ntiles; tile++) {
        const int kv0 = tile * FBN;
        const bool diag = (tile >= ntiles - 2);

        __syncthreads();   // protect Ks/Vs (loads below) and Ps (PV read prev iter)

        // ---- load K tile transposed: Ks[d][n] ----
        {
            const int n  = tid >> 2;              // 0..63
            const int d0 = (tid & 3) * 16;        // 0,16,32,48
            const float* kp = kbase + (size_t)(kv0 + n) * HD + d0;
#pragma unroll
            for (int i = 0; i < 4; i++) {
                float4 v4 = *(const float4*)(kp + i * 4);
                Ks[(d0 + i*4 + 0) * KSL + n] = v4.x;
                Ks[(d0 + i*4 + 1) * KSL + n] = v4.y;
                Ks[(d0 + i*4 + 2) * KSL + n] = v4.z;
                Ks[(d0 + i*4 + 3) * KSL + n] = v4.w;
            }
        }
        // ---- load V tile natural: Vs[kv][d] ----
#pragma unroll
        for (int i = 0; i < 4; i++) {
            const int idx = i * 256 + tid;        // float4 index 0..1023
            const int r = idx >> 4;
            const int c = (idx & 15) * 4;
            *(float4*)&Vs[r * 64 + c] =
                *(const float4*)(vbase + (size_t)(kv0 + r) * HD + c);
        }
        __syncthreads();

        // ---- S = (Q*scale) @ K^T : micro-tile 8x4 ----
        float s[8][4];
#pragma unroll
        for (int i = 0; i < 8; i++)
#pragma unroll
            for (int j = 0; j < 4; j++) s[i][j] = 0.f;

#pragma unroll 4
        for (int k = 0; k < 64; k++) {
            float af[8], bf[4];
            *(float4*)&af[0] = *(const float4*)&Qs[k * FBM + ty * 8];
            *(float4*)&af[4] = *(const float4*)&Qs[k * FBM + ty * 8 + 4];
            *(float4*)&bf[0] = *(const float4*)&Ks[k * KSL + tx * 4];
#pragma unroll
            for (int i = 0; i < 8; i++)
#pragma unroll
                for (int j = 0; j < 4; j++)
                    s[i][j] += af[i] * bf[j];
        }

        // ---- causal mask (diagonal tiles only) ----
        if (diag) {
            const int qrow0 = qt * FBM + ty * 8;
            const int key0  = kv0 + tx * 4;
#pragma unroll
            for (int i = 0; i < 8; i++)
#pragma unroll
                for (int j = 0; j < 4; j++)
                    if (key0 + j > qrow0 + i) s[i][j] = -1e30f;
        }

        // ---- online softmax: row max across 4 local + 16 tx lanes ----
#pragma unroll
        for (int i = 0; i < 8; i++) {
            float mt = fmaxf(fmaxf(s[i][0], s[i][1]), fmaxf(s[i][2], s[i][3]));
#pragma unroll
            for (int off = 1; off < 16; off <<= 1)
                mt = fmaxf(mt, __shfl_xor_sync(0xffffffffu, mt, off));
            const float mnew = fmaxf(mrow[i], mt);
            const float alpha = __expf(mrow[i] - mnew);
            mrow[i] = mnew;
            lrow[i] *= alpha;
#pragma unroll
            for (int j = 0; j < 4; j++) oacc[i][j] *= alpha;
            // p = exp(s - mnew); accumulate partial row sum; stage into Ps
            float4 pv;
            pv.x = __expf(s[i][0] - mnew);
            pv.y = __expf(s[i][1] - mnew);
            pv.z = __expf(s[i][2] - mnew);
            pv.w = __expf(s[i][3] - mnew);
            lrow[i] += pv.x + pv.y + pv.z + pv.w;
            *(float4*)&Ps[(ty * 8 + i) * PSL + tx * 4] = pv;
        }
        __syncthreads();

        // ---- O += P @ V : micro-tile 8 rows x 4 dims ----
#pragma unroll 2
        for (int kc = 0; kc < 64; kc += 4) {
            float4 vb0 = *(const float4*)&Vs[(kc + 0) * 64 + tx * 4];
            float4 vb1 = *(const float4*)&Vs[(kc + 1) * 64 + tx * 4];
            float4 vb2 = *(const float4*)&Vs[(kc + 2) * 64 + tx * 4];
            float4 vb3 = *(const float4*)&Vs[(kc + 3) * 64 + tx * 4];
#pragma unroll
            for (int i = 0; i < 8; i++) {
                float4 pf = *(const float4*)&Ps[(ty * 8 + i) * PSL + kc];
                oacc[i][0] += pf.x * vb0.x + pf.y * vb1.x + pf.z * vb2.x + pf.w * vb3.x;
                oacc[i][1] += pf.x * vb0.y + pf.y * vb1.y + pf.z * vb2.y + pf.w * vb3.y;
                oacc[i][2] += pf.x * vb0.z + pf.y * vb1.z + pf.z * vb2.z + pf.w * vb3.z;
                oacc[i][3] += pf.x * vb0.w + pf.y * vb1.w + pf.z * vb2.w + pf.w * vb3.w;
            }
        }
    }

    // ---- final: reduce lrow across tx lanes, normalize, store ----
#pragma unroll
    for (int i = 0; i < 8; i++) {
#pragma unroll
        for (int off = 1; off < 16; off <<= 1)
            lrow[i] += __shfl_xor_sync(0xffffffffu, lrow[i], off);
        const float inv = 1.f / lrow[i];
        const int m = qt * FBM + ty * 8 + i;
        float4 r;
        r.x = oacc[i][0] * inv;
        r.y = oacc[i][1] * inv;
        r.z = oacc[i][2] * inv;
        r.w = oacc[i][3] * inv;
        *(float4*)(O + head_base + (size_t)m * HD + tx * 4) = r;
    }
}

// ---------------------------------------------------------------------------
extern "C" void kernel_launch(void* const* d_in, const int* in_sizes, int n_in,
                              void* d_out, int out_size)
{
    const float* x  = (const float*)d_in[0];
    const float* Wq = (const float*)d_in[1];
    const float* bq = (const float*)d_in[2];
    const float* Wk = (const float*)d_in[3];
    const float* bk = (const float*)d_in[4];
    const float* Wv = (const float*)d_in[5];
    const float* bv = (const float*)d_in[6];
    const float* Wo = (const float*)d_in[7];
    const float* bo = (const float*)d_in[8];
    float* out = (float*)d_out;

    float *q, *k, *v, *ao;
    cudaGetSymbolAddress((void**)&q,  g_q);
    cudaGetSymbolAddress((void**)&k,  g_k);
    cudaGetSymbolAddress((void**)&v,  g_v);
    cudaGetSymbolAddress((void**)&ao, g_ao);

    dim3 gemm_grid(CC / 128, MROWS / 128);
    dim3 gemm_blk(256);

    gemm128<false, true><<<gemm_grid, gemm_blk>>>(x, Wq, bq, q, MROWS, CC, CC);
    gemm128<false, true><<<gemm_grid, gemm_blk>>>(x, Wk, bk, k, MROWS, CC, CC);
    gemm128<false, true><<<gemm_grid, gemm_blk>>>(x, Wv, bv, v, MROWS, CC, CC);

    const int flash_smem = FLASH_SMEM_FLOATS * sizeof(float);  // ~99 KB
    static bool attr_set = false;
    if (!attr_set) {
        cudaFuncSetAttribute(flash2, cudaFuncAttributeMaxDynamicSharedMemorySize,
                             flash_smem);
        attr_set = true;
    }
    dim3 att_grid(TT / 128, HH, BB);
    flash2<<<att_grid, 256, flash_smem>>>(q, k, v, ao);

    gemm128<true, false><<<gemm_grid, gemm_blk>>>(ao, Wo, bo, out, MROWS, CC, CC);
}

// round 5
// speedup vs baseline: 1.7554x; 1.4581x over previous
#include <cuda_runtime.h>
#include <cuda_bf16.h>
#include <stdint.h>
#include <math.h>

// Problem constants
#define BB 2
#define TT 2048
#define CC 1024
#define HH 16
#define HD 64
#define MROWS (BB*TT)

// ---------------------------------------------------------------------------
// Scratch (allocation-free rule: __device__ globals)
// ---------------------------------------------------------------------------
__device__ float g_q [MROWS*CC];
__device__ float g_k [MROWS*CC];
__device__ float g_v [MROWS*CC];
__device__ float g_ao[MROWS*CC];
__device__ __nv_bfloat16 g_xh [MROWS*CC];
__device__ __nv_bfloat16 g_xl [MROWS*CC];
__device__ __nv_bfloat16 g_aoh[MROWS*CC];
__device__ __nv_bfloat16 g_aol[MROWS*CC];
__device__ __nv_bfloat16 g_wt [8*CC*CC];   // [w*2+{hi,lo}][n][k]  (W^T, K-major)

// ---------------------------------------------------------------------------
// Warp-MMA helpers (base sm_80+ features; no tcgen05 on .target sm_103)
// ---------------------------------------------------------------------------
__device__ __forceinline__ uint32_t s2u(const void* p) {
    uint32_t a;
    asm("{ .reg .u64 t; cvta.to.shared.u64 t, %1; cvt.u32.u64 %0, t; }"
        : "=r"(a) : "l"(p));
    return a;
}
__device__ __forceinline__ void ldsm_x4(uint32_t* r, uint32_t addr) {
    asm volatile("ldmatrix.sync.aligned.m8n8.x4.shared.b16 {%0,%1,%2,%3}, [%4];"
        : "=r"(r[0]), "=r"(r[1]), "=r"(r[2]), "=r"(r[3]) : "r"(addr));
}
__device__ __forceinline__ void mma16816(float* c, const uint32_t* a, const uint32_t* b) {
    asm volatile(
        "mma.sync.aligned.m16n8k16.row.col.f32.bf16.bf16.f32 "
        "{%0,%1,%2,%3}, {%4,%5,%6,%7}, {%8,%9}, {%0,%1,%2,%3};"
        : "+f"(c[0]), "+f"(c[1]), "+f"(c[2]), "+f"(c[3])
        : "r"(a[0]), "r"(a[1]), "r"(a[2]), "r"(a[3]), "r"(b[0]), "r"(b[1]));
}
__device__ __forceinline__ void cpa16(uint32_t dst, const void* src) {
    asm volatile("cp.async.ca.shared.global [%0], [%1], 16;" :: "r"(dst), "l"(src));
}

// ---------------------------------------------------------------------------
// Prep kernels (fp32 -> bf16 hi/lo splits)
// ---------------------------------------------------------------------------
__device__ __forceinline__ void split1(float v, __nv_bfloat16& h, __nv_bfloat16& l) {
    h = __float2bfloat16_rn(v);
    l = __float2bfloat16_rn(v - __bfloat162float(h));
}
__device__ __forceinline__ uint32_t pk2(__nv_bfloat16 a, __nv_bfloat16 b) {
    return (uint32_t)__bfloat16_as_ushort(a) | ((uint32_t)__bfloat16_as_ushort(b) << 16);
}

__global__ void splitx(const float* __restrict__ x,
                       __nv_bfloat16* __restrict__ hi, __nv_bfloat16* __restrict__ lo)
{
    const int i = blockIdx.x * blockDim.x + threadIdx.x;   // over MROWS*CC/4
    float4 v = ((const float4*)x)[i];
    __nv_bfloat16 h0,h1,h2,h3,l0,l1,l2,l3;
    split1(v.x,h0,l0); split1(v.y,h1,l1); split1(v.z,h2,l2); split1(v.w,h3,l3);
    uint2 hw = { pk2(h0,h1), pk2(h2,h3) };
    uint2 lw = { pk2(l0,l1), pk2(l2,l3) };
    ((uint2*)hi)[i] = hw;
    ((uint2*)lo)[i] = lw;
}

// W [K=1024][N=1024] -> W^T hi/lo [N][K]
__global__ __launch_bounds__(256)
void wsplit(const float* __restrict__ W,
            __nv_bfloat16* __restrict__ th, __nv_bfloat16* __restrict__ tl)
{
    __shared__ float t[32][33];
    const int n0 = blockIdx.x * 32;
    const int k0 = blockIdx.y * 32;
    const int tx = threadIdx.x & 31;
    const int ty = threadIdx.x >> 5;   // 0..7
#pragma unroll
    for (int r = 0; r < 4; r++) {
        const int row = ty + r * 8;
        t[row][tx] = W[(size_t)(k0 + row) * CC + n0 + tx];
    }
    __syncthreads();
#pragma unroll
    for (int r = 0; r < 4; r++) {
        const int row = ty + r * 8;          // local n
        const float v = t[tx][row];          // = W[k0+tx][n0+row]
        __nv_bfloat16 h, l;
        split1(v, h, l);
        th[(size_t)(n0 + row) * CC + k0 + tx] = h;
        tl[(size_t)(n0 + row) * CC + k0 + tx] = l;
    }
}

// attention output [B,H,T,HD] fp32 -> logical [B*T, H*HD] bf16 hi/lo
__global__ void split_ao(const float* __restrict__ src,
                         __nv_bfloat16* __restrict__ hi, __nv_bfloat16* __restrict__ lo)
{
    const int i = blockIdx.x * blockDim.x + threadIdx.x;   // over MROWS*CC/4
    float4 v = ((const float4*)src)[i];
    const int d4 = i & 15;
    const int t  = (i >> 4) & (TT - 1);
    const int h  = (i >> 15) & (HH - 1);
    const int b  = i >> 19;
    const size_t dst4 = (((size_t)(b * TT + t) * CC) + h * HD + d4 * 4) >> 2;
    __nv_bfloat16 h0,h1,h2,h3,l0,l1,l2,l3;
    split1(v.x,h0,l0); split1(v.y,h1,l1); split1(v.z,h2,l2); split1(v.w,h3,l3);
    uint2 hw = { pk2(h0,h1), pk2(h2,h3) };
    uint2 lw = { pk2(l0,l1), pk2(l2,l3) };
    ((uint2*)hi)[dst4] = hw;
    ((uint2*)lo)[dst4] = lw;
}

// ---------------------------------------------------------------------------
// mma.sync split-bf16 GEMM: Y[4096,1024] = A@W + bias (fp32 out)
//   A = Ah + Al [M][K] bf16 ; W^T = Bh + Bl [N][K] bf16
//   Y = Ah*Bh + Ah*Bl + Al*Bh (fp32 accumulate in registers)
// CTA tile 128x128, 8 warps (2m x 4n), warp tile 64x32 (4 x 4 m16n8 tiles),
// K chunks of 16, cp.async double buffer. grid (8, 32).
// ---------------------------------------------------------------------------
#define KC 16
#define TSTRIDE 48                       // smem row stride bytes (32B data + 16B pad)
#define TILE_B (128*TSTRIDE)             // 6144
#define BUF_B  (4*TILE_B)                // 24576 (Ah,Al,Bh,Bl)
#define GEMM_SMEM (2*BUF_B)              // 49152

template<bool OUT_PERM>
__global__ __launch_bounds__(256, 2)
void mmagemm(const __nv_bfloat16* __restrict__ Ah, const __nv_bfloat16* __restrict__ Al,
             const __nv_bfloat16* __restrict__ Bh, const __nv_bfloat16* __restrict__ Bl,
             const float* __restrict__ bias, float* __restrict__ Y)
{
    extern __shared__ char dsm[];
    const uint32_t sb = s2u(dsm);

    const int tid = threadIdx.x;
    const int lane = tid & 31;
    const int wid = tid >> 5;
    const int warp_m = wid & 1;          // 0..1 (64 rows each)
    const int warp_n = wid >> 1;         // 0..3 (32 cols each)
    const int bm = blockIdx.y * 128;
    const int bn = blockIdx.x * 128;

    float acc[4][4][4];
#pragma unroll
    for (int i = 0; i < 4; i++)
#pragma unroll
        for (int j = 0; j < 4; j++)
#pragma unroll
            for (int q = 0; q < 4; q++) acc[i][j][q] = 0.f;

    // cp.async issue for chunk c (1024 x 16B ops, 4 per thread)
    auto issue = [&](int c) {
        const int k0 = c * KC;
        const uint32_t bu = sb + (c & 1) * BUF_B;
        const int r = (tid * 2) >> 1;    // helper noop to keep indices simple
        (void)r;
#pragma unroll
        for (int i = 0; i < 4; i++) {
            const int j = i * 256 + tid;         // 0..1023
            const int row = (j >> 1) & 127;
            const int seg = j & 1;
            const __nv_bfloat16* s = (i == 0) ? Ah : (i == 1) ? Al : (i == 2) ? Bh : Bl;
            const int rb = (i < 2) ? bm : bn;
            cpa16(bu + i * TILE_B + row * TSTRIDE + seg * 16,
                  s + (size_t)(rb + row) * CC + k0 + seg * 8);
        }
        asm volatile("cp.async.commit_group;" ::: "memory");
    };

    issue(0);
    issue(1);

    // ldmatrix lane address offsets (within a tile)
    const uint32_t a_off = (uint32_t)((warp_m * 64 + (lane & 15)) * TSTRIDE
                                      + (lane >> 4) * 16);
    const uint32_t b_off = (uint32_t)((warp_n * 32 + ((lane >> 4) * 8) + (lane & 7)) * TSTRIDE
                                      + ((lane >> 3) & 1) * 16);

    for (int c = 0; c < 64; c++) {
        if (c == 63) asm volatile("cp.async.wait_group 0;" ::: "memory");
        else         asm volatile("cp.async.wait_group 1;" ::: "memory");
        __syncthreads();

        const uint32_t bu = sb + (c & 1) * BUF_B;
        uint32_t af[4][4];
        uint32_t bf[2][4];   // bf[p] covers n-tiles 2p, 2p+1

        // ---- pass 1: Ah x Bh ----
#pragma unroll
        for (int mt = 0; mt < 4; mt++)
            ldsm_x4(af[mt], bu + a_off + (uint32_t)(mt * 16 * TSTRIDE));
#pragma unroll
        for (int p = 0; p < 2; p++)
            ldsm_x4(bf[p], bu + 2*TILE_B + b_off + (uint32_t)(p * 16 * TSTRIDE));
#pragma unroll
        for (int mt = 0; mt < 4; mt++)
#pragma unroll
            for (int nt = 0; nt < 4; nt++)
                mma16816(acc[mt][nt], af[mt], &bf[nt >> 1][(nt & 1) * 2]);

        // ---- pass 2: Ah x Bl ----
#pragma unroll
        for (int p = 0; p < 2; p++)
            ldsm_x4(bf[p], bu + 3*TILE_B + b_off + (uint32_t)(p * 16 * TSTRIDE));
#pragma unroll
        for (int mt = 0; mt < 4; mt++)
#pragma unroll
            for (int nt = 0; nt < 4; nt++)
                mma16816(acc[mt][nt], af[mt], &bf[nt >> 1][(nt & 1) * 2]);

        // ---- pass 3: Al x Bh ----
#pragma unroll
        for (int mt = 0; mt < 4; mt++)
            ldsm_x4(af[mt], bu + TILE_B + a_off + (uint32_t)(mt * 16 * TSTRIDE));
#pragma unroll
        for (int p = 0; p < 2; p++)
            ldsm_x4(bf[p], bu + 2*TILE_B + b_off + (uint32_t)(p * 16 * TSTRIDE));
#pragma unroll
        for (int mt = 0; mt < 4; mt++)
#pragma unroll
            for (int nt = 0; nt < 4; nt++)
                mma16816(acc[mt][nt], af[mt], &bf[nt >> 1][(nt & 1) * 2]);

        __syncthreads();
        if (c + 2 < 64) issue(c + 2);
    }

    // ---- epilogue: bias add + store (optionally permuted to [B,H,T,HD]) ----
#pragma unroll
    for (int mt = 0; mt < 4; mt++) {
#pragma unroll
        for (int nt = 0; nt < 4; nt++) {
            const int m0 = bm + warp_m * 64 + mt * 16 + (lane >> 2);
            const int n0 = bn + warp_n * 32 + nt * 8 + 2 * (lane & 3);
            const float b0 = __ldg(bias + n0);
            const float b1 = __ldg(bias + n0 + 1);
#pragma unroll
            for (int half = 0; half < 2; half++) {
                const int m = m0 + half * 8;
                const int bb = m >> 11;
                const int tt = m & (TT - 1);
                float2 r;
                r.x = acc[mt][nt][half * 2 + 0] + b0;
                r.y = acc[mt][nt][half * 2 + 1] + b1;
                float* yp;
                if (OUT_PERM) {
                    const int h = n0 >> 6;
                    const int d = n0 & (HD - 1);
                    yp = Y + ((((size_t)bb * HH + h) * TT + tt) * HD + d);
                } else {
                    yp = Y + (size_t)m * CC + n0;
                }
                *(float2*)yp = r;
            }
        }
    }
}

// ---------------------------------------------------------------------------
// Block-tiled flash attention (fp32) — unchanged from round 3
// ---------------------------------------------------------------------------
#define FBM 128
#define FBN 64
#define KSL 68
#define PSL 68
#define FLASH_SMEM_FLOATS (64*FBM + 64*KSL + 64*64 + FBM*PSL)

__global__ __launch_bounds__(256)
void flash2(const float* __restrict__ Q, const float* __restrict__ Kg,
            const float* __restrict__ Vg, float* __restrict__ O)
{
    extern __shared__ float sm[];
    float* Qs = sm;
    float* Ks = Qs + 64 * FBM;
    float* Vs = Ks + 64 * KSL;
    float* Ps = Vs + 64 * 64;

    const int tid = threadIdx.x;
    const int ty = tid >> 4;
    const int tx = tid & 15;
    const int qt = blockIdx.x;
    const int h  = blockIdx.y;
    const int b  = blockIdx.z;

    const size_t head_base = (((size_t)b * HH + h) * TT) * HD;
    const float scale = 0.125f;

    {
        const int m  = tid & 127;
        const int d0 = (tid >> 7) * 32;
        const float* qp = Q + head_base + (size_t)(qt * FBM + m) * HD + d0;
#pragma unroll
        for (int i = 0; i < 8; i++) {
            float4 v4 = *(const float4*)(qp + i * 4);
            Qs[(d0 + i*4 + 0) * FBM + m] = v4.x * scale;
            Qs[(d0 + i*4 + 1) * FBM + m] = v4.y * scale;
            Qs[(d0 + i*4 + 2) * FBM + m] = v4.z * scale;
            Qs[(d0 + i*4 + 3) * FBM + m] = v4.w * scale;
        }
    }

    float mrow[8], lrow[8], oacc[8][4];
#pragma unroll
    for (int i = 0; i < 8; i++) {
        mrow[i] = -1e30f;
        lrow[i] = 0.f;
#pragma unroll
        for (int j = 0; j < 4; j++) oacc[i][j] = 0.f;
    }

    const float* kbase = Kg + head_base;
    const float* vbase = Vg + head_base;
    const int ntiles = (qt + 1) * 2;

    for (int tile = 0; tile < ntiles; tile++) {
        const int kv0 = tile * FBN;
        const bool diag = (tile >= ntiles - 2);

        __syncthreads();

        {
            const int n  = tid >> 2;
            const int d0 = (tid & 3) * 16;
            const float* kp = kbase + (size_t)(kv0 + n) * HD + d0;
#pragma unroll
            for (int i = 0; i < 4; i++) {
                float4 v4 = *(const float4*)(kp + i * 4);
                Ks[(d0 + i*4 + 0) * KSL + n] = v4.x;
                Ks[(d0 + i*4 + 1) * KSL + n] = v4.y;
                Ks[(d0 + i*4 + 2) * KSL + n] = v4.z;
                Ks[(d0 + i*4 + 3) * KSL + n] = v4.w;
            }
        }
#pragma unroll
        for (int i = 0; i < 4; i++) {
            const int idx = i * 256 + tid;
            const int r = idx >> 4;
            const int c = (idx & 15) * 4;
            *(float4*)&Vs[r * 64 + c] =
                *(const float4*)(vbase + (size_t)(kv0 + r) * HD + c);
        }
        __syncthreads();

        float s[8][4];
#pragma unroll
        for (int i = 0; i < 8; i++)
#pragma unroll
            for (int j = 0; j < 4; j++) s[i][j] = 0.f;

#pragma unroll 4
        for (int k = 0; k < 64; k++) {
            float af[8], bf[4];
            *(float4*)&af[0] = *(const float4*)&Qs[k * FBM + ty * 8];
            *(float4*)&af[4] = *(const float4*)&Qs[k * FBM + ty * 8 + 4];
            *(float4*)&bf[0] = *(const float4*)&Ks[k * KSL + tx * 4];
#pragma unroll
            for (int i = 0; i < 8; i++)
#pragma unroll
                for (int j = 0; j < 4; j++)
                    s[i][j] += af[i] * bf[j];
        }

        if (diag) {
            const int qrow0 = qt * FBM + ty * 8;
            const int key0  = kv0 + tx * 4;
#pragma unroll
            for (int i = 0; i < 8; i++)
#pragma unroll
                for (int j = 0; j < 4; j++)
                    if (key0 + j > qrow0 + i) s[i][j] = -1e30f;
        }

#pragma unroll
        for (int i = 0; i < 8; i++) {
            float mt = fmaxf(fmaxf(s[i][0], s[i][1]), fmaxf(s[i][2], s[i][3]));
#pragma unroll
            for (int off = 1; off < 16; off <<= 1)
                mt = fmaxf(mt, __shfl_xor_sync(0xffffffffu, mt, off));
            const float mnew = fmaxf(mrow[i], mt);
            const float alpha = __expf(mrow[i] - mnew);
            mrow[i] = mnew;
            lrow[i] *= alpha;
#pragma unroll
            for (int j = 0; j < 4; j++) oacc[i][j] *= alpha;
            float4 pv;
            pv.x = __expf(s[i][0] - mnew);
            pv.y = __expf(s[i][1] - mnew);
            pv.z = __expf(s[i][2] - mnew);
            pv.w = __expf(s[i][3] - mnew);
            lrow[i] += pv.x + pv.y + pv.z + pv.w;
            *(float4*)&Ps[(ty * 8 + i) * PSL + tx * 4] = pv;
        }
        __syncthreads();

#pragma unroll 2
        for (int kc = 0; kc < 64; kc += 4) {
            float4 vb0 = *(const float4*)&Vs[(kc + 0) * 64 + tx * 4];
            float4 vb1 = *(const float4*)&Vs[(kc + 1) * 64 + tx * 4];
            float4 vb2 = *(const float4*)&Vs[(kc + 2) * 64 + tx * 4];
            float4 vb3 = *(const float4*)&Vs[(kc + 3) * 64 + tx * 4];
#pragma unroll
            for (int i = 0; i < 8; i++) {
                float4 pf = *(const float4*)&Ps[(ty * 8 + i) * PSL + kc];
                oacc[i][0] += pf.x * vb0.x + pf.y * vb1.x + pf.z * vb2.x + pf.w * vb3.x;
                oacc[i][1] += pf.x * vb0.y + pf.y * vb1.y + pf.z * vb2.y + pf.w * vb3.y;
                oacc[i][2] += pf.x * vb0.z + pf.y * vb1.z + pf.z * vb2.z + pf.w * vb3.z;
                oacc[i][3] += pf.x * vb0.w + pf.y * vb1.w + pf.z * vb2.w + pf.w * vb3.w;
            }
        }
    }

#pragma unroll
    for (int i = 0; i < 8; i++) {
#pragma unroll
        for (int off = 1; off < 16; off <<= 1)
            lrow[i] += __shfl_xor_sync(0xffffffffu, lrow[i], off);
        const float inv = 1.f / lrow[i];
        const int m = qt * FBM + ty * 8 + i;
        float4 r;
        r.x = oacc[i][0] * inv;
        r.y = oacc[i][1] * inv;
        r.z = oacc[i][2] * inv;
        r.w = oacc[i][3] * inv;
        *(float4*)(O + head_base + (size_t)m * HD + tx * 4) = r;
    }
}

// ---------------------------------------------------------------------------
extern "C" void kernel_launch(void* const* d_in, const int* in_sizes, int n_in,
                              void* d_out, int out_size)
{
    const float* x  = (const float*)d_in[0];
    const float* Wq = (const float*)d_in[1];
    const float* bq = (const float*)d_in[2];
    const float* Wk = (const float*)d_in[3];
    const float* bk = (const float*)d_in[4];
    const float* Wv = (const float*)d_in[5];
    const float* bv = (const float*)d_in[6];
    const float* Wo = (const float*)d_in[7];
    const float* bo = (const float*)d_in[8];
    float* out = (float*)d_out;

    float *q, *k, *v, *ao;
    __nv_bfloat16 *xh, *xl, *aoh, *aol, *wt;
    cudaGetSymbolAddress((void**)&q,   g_q);
    cudaGetSymbolAddress((void**)&k,   g_k);
    cudaGetSymbolAddress((void**)&v,   g_v);
    cudaGetSymbolAddress((void**)&ao,  g_ao);
    cudaGetSymbolAddress((void**)&xh,  g_xh);
    cudaGetSymbolAddress((void**)&xl,  g_xl);
    cudaGetSymbolAddress((void**)&aoh, g_aoh);
    cudaGetSymbolAddress((void**)&aol, g_aol);
    cudaGetSymbolAddress((void**)&wt,  g_wt);

    static bool attr_set = false;
    if (!attr_set) {
        cudaFuncSetAttribute(flash2, cudaFuncAttributeMaxDynamicSharedMemorySize,
                             FLASH_SMEM_FLOATS * sizeof(float));
        cudaFuncSetAttribute(mmagemm<true>, cudaFuncAttributeMaxDynamicSharedMemorySize,
                             GEMM_SMEM);
        cudaFuncSetAttribute(mmagemm<false>, cudaFuncAttributeMaxDynamicSharedMemorySize,
                             GEMM_SMEM);
        attr_set = true;
    }

    const int n4 = MROWS * CC / 4;       // 1M float4
    splitx<<<n4 / 256, 256>>>(x, xh, xl);

    dim3 wgrid(CC / 32, CC / 32);        // (32,32)
    wsplit<<<wgrid, 256>>>(Wq, wt + 0*CC*CC, wt + 1*CC*CC);
    wsplit<<<wgrid, 256>>>(Wk, wt + 2*CC*CC, wt + 3*CC*CC);
    wsplit<<<wgrid, 256>>>(Wv, wt + 4*CC*CC, wt + 5*CC*CC);
    wsplit<<<wgrid, 256>>>(Wo, wt + 6*CC*CC, wt + 7*CC*CC);

    dim3 ggrid(CC / 128, MROWS / 128);   // (8, 32)
    mmagemm<true><<<ggrid, 256, GEMM_SMEM>>>(xh, xl, wt + 0*CC*CC, wt + 1*CC*CC, bq, q);
    mmagemm<true><<<ggrid, 256, GEMM_SMEM>>>(xh, xl, wt + 2*CC*CC, wt + 3*CC*CC, bk, k);
    mmagemm<true><<<ggrid, 256, GEMM_SMEM>>>(xh, xl, wt + 4*CC*CC, wt + 5*CC*CC, bv, v);

    dim3 att_grid(TT / 128, HH, BB);
    flash2<<<att_grid, 256, FLASH_SMEM_FLOATS * sizeof(float)>>>(q, k, v, ao);

    split_ao<<<n4 / 256, 256>>>(ao, aoh, aol);
    mmagemm<false><<<ggrid, 256, GEMM_SMEM>>>(aoh, aol, wt + 6*CC*CC, wt + 7*CC*CC, bo, out);
}

// round 6
// speedup vs baseline: 2.9874x; 1.7018x over previous
#include <cuda_runtime.h>
#include <cuda_bf16.h>
#include <stdint.h>
#include <math.h>

// Problem constants
#define BB 2
#define TT 2048
#define CC 1024
#define HH 16
#define HD 64
#define MROWS (BB*TT)

// ---------------------------------------------------------------------------
// Scratch (allocation-free rule: __device__ globals)
// ---------------------------------------------------------------------------
__device__ __nv_bfloat16 g_xh [MROWS*CC];
__device__ __nv_bfloat16 g_xl [MROWS*CC];
__device__ __nv_bfloat16 g_qh [MROWS*CC];
__device__ __nv_bfloat16 g_ql [MROWS*CC];
__device__ __nv_bfloat16 g_kh [MROWS*CC];
__device__ __nv_bfloat16 g_kl [MROWS*CC];
__device__ __nv_bfloat16 g_vh [MROWS*CC];
__device__ __nv_bfloat16 g_vl [MROWS*CC];
__device__ __nv_bfloat16 g_aoh[MROWS*CC];
__device__ __nv_bfloat16 g_aol[MROWS*CC];
__device__ __nv_bfloat16 g_wt [8*CC*CC];   // [w*2+{hi,lo}][n][k]  (W^T, K-major)

// ---------------------------------------------------------------------------
// Warp-MMA helpers (base sm_80+ features)
// ---------------------------------------------------------------------------
__device__ __forceinline__ uint32_t s2u(const void* p) {
    uint32_t a;
    asm("{ .reg .u64 t; cvta.to.shared.u64 t, %1; cvt.u32.u64 %0, t; }"
        : "=r"(a) : "l"(p));
    return a;
}
__device__ __forceinline__ void ldsm_x4(uint32_t* r, uint32_t addr) {
    asm volatile("ldmatrix.sync.aligned.m8n8.x4.shared.b16 {%0,%1,%2,%3}, [%4];"
        : "=r"(r[0]), "=r"(r[1]), "=r"(r[2]), "=r"(r[3]) : "r"(addr));
}
__device__ __forceinline__ void ldsm_x4t(uint32_t* r, uint32_t addr) {
    asm volatile("ldmatrix.sync.aligned.m8n8.x4.trans.shared.b16 {%0,%1,%2,%3}, [%4];"
        : "=r"(r[0]), "=r"(r[1]), "=r"(r[2]), "=r"(r[3]) : "r"(addr));
}
__device__ __forceinline__ void mma16816(float* c, const uint32_t* a, const uint32_t* b) {
    asm volatile(
        "mma.sync.aligned.m16n8k16.row.col.f32.bf16.bf16.f32 "
        "{%0,%1,%2,%3}, {%4,%5,%6,%7}, {%8,%9}, {%0,%1,%2,%3};"
        : "+f"(c[0]), "+f"(c[1]), "+f"(c[2]), "+f"(c[3])
        : "r"(a[0]), "r"(a[1]), "r"(a[2]), "r"(a[3]), "r"(b[0]), "r"(b[1]));
}
__device__ __forceinline__ void cpa16(uint32_t dst, const void* src) {
    asm volatile("cp.async.ca.shared.global [%0], [%1], 16;" :: "r"(dst), "l"(src));
}
#define CP_COMMIT() asm volatile("cp.async.commit_group;" ::: "memory")
#define CP_WAIT(n)  asm volatile("cp.async.wait_group %0;" :: "n"(n) : "memory")

__device__ __forceinline__ void split1(float v, __nv_bfloat16& h, __nv_bfloat16& l) {
    h = __float2bfloat16_rn(v);
    l = __float2bfloat16_rn(v - __bfloat162float(h));
}
__device__ __forceinline__ uint32_t pk2(__nv_bfloat16 a, __nv_bfloat16 b) {
    return (uint32_t)__bfloat16_as_ushort(a) | ((uint32_t)__bfloat16_as_ushort(b) << 16);
}
__device__ __forceinline__ void splitpack(float a, float b, uint32_t& hi, uint32_t& lo) {
    __nv_bfloat16 ah, al, bh, bl;
    split1(a, ah, al); split1(b, bh, bl);
    hi = pk2(ah, bh); lo = pk2(al, bl);
}

// ---------------------------------------------------------------------------
// Prep kernels
// ---------------------------------------------------------------------------
__global__ void splitx(const float* __restrict__ x,
                       __nv_bfloat16* __restrict__ hi, __nv_bfloat16* __restrict__ lo)
{
    const int i = blockIdx.x * blockDim.x + threadIdx.x;
    float4 v = ((const float4*)x)[i];
    __nv_bfloat16 h0,h1,h2,h3,l0,l1,l2,l3;
    split1(v.x,h0,l0); split1(v.y,h1,l1); split1(v.z,h2,l2); split1(v.w,h3,l3);
    uint2 hw = { pk2(h0,h1), pk2(h2,h3) };
    uint2 lw = { pk2(l0,l1), pk2(l2,l3) };
    ((uint2*)hi)[i] = hw;
    ((uint2*)lo)[i] = lw;
}

__global__ __launch_bounds__(256)
void wsplit(const float* __restrict__ W,
            __nv_bfloat16* __restrict__ th, __nv_bfloat16* __restrict__ tl)
{
    __shared__ float t[32][33];
    const int n0 = blockIdx.x * 32;
    const int k0 = blockIdx.y * 32;
    const int tx = threadIdx.x & 31;
    const int ty = threadIdx.x >> 5;
#pragma unroll
    for (int r = 0; r < 4; r++) {
        const int row = ty + r * 8;
        t[row][tx] = W[(size_t)(k0 + row) * CC + n0 + tx];
    }
    __syncthreads();
#pragma unroll
    for (int r = 0; r < 4; r++) {
        const int row = ty + r * 8;
        const float v = t[tx][row];
        __nv_bfloat16 h, l;
        split1(v, h, l);
        th[(size_t)(n0 + row) * CC + k0 + tx] = h;
        tl[(size_t)(n0 + row) * CC + k0 + tx] = l;
    }
}

// ---------------------------------------------------------------------------
// mma.sync split-bf16 GEMM: Y = A@W + bias
// MODE 0: fp32 out [M][C] (final projection)
// MODE 1: bf16 hi/lo split out, permuted to [B,H,T,HD], scaled (QKV projections)
// ---------------------------------------------------------------------------
#define KC 16
#define TSTRIDE 48
#define TILE_B (128*TSTRIDE)
#define BUF_B  (4*TILE_B)
#define GEMM_SMEM (2*BUF_B)

template<int MODE>
__global__ __launch_bounds__(256, 2)
void mmagemm(const __nv_bfloat16* __restrict__ Ah, const __nv_bfloat16* __restrict__ Al,
             const __nv_bfloat16* __restrict__ Bh, const __nv_bfloat16* __restrict__ Bl,
             const float* __restrict__ bias, float* __restrict__ Y,
             __nv_bfloat16* __restrict__ Yh, __nv_bfloat16* __restrict__ Yl,
             float scale)
{
    extern __shared__ char dsm[];
    const uint32_t sb = s2u(dsm);

    const int tid = threadIdx.x;
    const int lane = tid & 31;
    const int wid = tid >> 5;
    const int warp_m = wid & 1;
    const int warp_n = wid >> 1;
    const int bm = blockIdx.y * 128;
    const int bn = blockIdx.x * 128;

    float acc[4][4][4];
#pragma unroll
    for (int i = 0; i < 4; i++)
#pragma unroll
        for (int j = 0; j < 4; j++)
#pragma unroll
            for (int q = 0; q < 4; q++) acc[i][j][q] = 0.f;

    auto issue = [&](int c) {
        const int k0 = c * KC;
        const uint32_t bu = sb + (c & 1) * BUF_B;
#pragma unroll
        for (int i = 0; i < 4; i++) {
            const int j = i * 256 + tid;
            const int row = (j >> 1) & 127;
            const int seg = j & 1;
            const __nv_bfloat16* s = (i == 0) ? Ah : (i == 1) ? Al : (i == 2) ? Bh : Bl;
            const int rb = (i < 2) ? bm : bn;
            cpa16(bu + i * TILE_B + row * TSTRIDE + seg * 16,
                  s + (size_t)(rb + row) * CC + k0 + seg * 8);
        }
        CP_COMMIT();
    };

    issue(0);
    issue(1);

    const uint32_t a_off = (uint32_t)((warp_m * 64 + (lane & 15)) * TSTRIDE
                                      + (lane >> 4) * 16);
    const uint32_t b_off = (uint32_t)((warp_n * 32 + ((lane >> 4) * 8) + (lane & 7)) * TSTRIDE
                                      + ((lane >> 3) & 1) * 16);

    for (int c = 0; c < 64; c++) {
        if (c == 63) CP_WAIT(0);
        else         CP_WAIT(1);
        __syncthreads();

        const uint32_t bu = sb + (c & 1) * BUF_B;
        uint32_t af[4][4];
        uint32_t bf[2][4];

#pragma unroll
        for (int mt = 0; mt < 4; mt++)
            ldsm_x4(af[mt], bu + a_off + (uint32_t)(mt * 16 * TSTRIDE));
#pragma unroll
        for (int p = 0; p < 2; p++)
            ldsm_x4(bf[p], bu + 2*TILE_B + b_off + (uint32_t)(p * 16 * TSTRIDE));
#pragma unroll
        for (int mt = 0; mt < 4; mt++)
#pragma unroll
            for (int nt = 0; nt < 4; nt++)
                mma16816(acc[mt][nt], af[mt], &bf[nt >> 1][(nt & 1) * 2]);

#pragma unroll
        for (int p = 0; p < 2; p++)
            ldsm_x4(bf[p], bu + 3*TILE_B + b_off + (uint32_t)(p * 16 * TSTRIDE));
#pragma unroll
        for (int mt = 0; mt < 4; mt++)
#pragma unroll
            for (int nt = 0; nt < 4; nt++)
                mma16816(acc[mt][nt], af[mt], &bf[nt >> 1][(nt & 1) * 2]);

#pragma unroll
        for (int mt = 0; mt < 4; mt++)
            ldsm_x4(af[mt], bu + TILE_B + a_off + (uint32_t)(mt * 16 * TSTRIDE));
#pragma unroll
        for (int p = 0; p < 2; p++)
            ldsm_x4(bf[p], bu + 2*TILE_B + b_off + (uint32_t)(p * 16 * TSTRIDE));
#pragma unroll
        for (int mt = 0; mt < 4; mt++)
#pragma unroll
            for (int nt = 0; nt < 4; nt++)
                mma16816(acc[mt][nt], af[mt], &bf[nt >> 1][(nt & 1) * 2]);

        __syncthreads();
        if (c + 2 < 64) issue(c + 2);
    }

#pragma unroll
    for (int mt = 0; mt < 4; mt++) {
#pragma unroll
        for (int nt = 0; nt < 4; nt++) {
            const int m0 = bm + warp_m * 64 + mt * 16 + (lane >> 2);
            const int n0 = bn + warp_n * 32 + nt * 8 + 2 * (lane & 3);
            const float b0 = __ldg(bias + n0);
            const float b1 = __ldg(bias + n0 + 1);
#pragma unroll
            for (int half = 0; half < 2; half++) {
                const int m = m0 + half * 8;
                const int bb = m >> 11;
                const int tt = m & (TT - 1);
                const float v0 = (acc[mt][nt][half * 2 + 0] + b0) * scale;
                const float v1 = (acc[mt][nt][half * 2 + 1] + b1) * scale;
                if (MODE == 0) {
                    float2 r; r.x = v0; r.y = v1;
                    *(float2*)(Y + (size_t)m * CC + n0) = r;
                } else {
                    const int h = n0 >> 6;
                    const int d = n0 & (HD - 1);
                    const size_t dst = (((size_t)bb * HH + h) * TT + tt) * HD + d;
                    uint32_t hw, lw;
                    splitpack(v0, v1, hw, lw);
                    *(uint32_t*)(Yh + dst) = hw;
                    *(uint32_t*)(Yl + dst) = lw;
                }
            }
        }
    }
}

// ---------------------------------------------------------------------------
// flash3: FA2-style mma.sync causal attention, split-bf16 everywhere.
// CTA: 128 q-rows, 8 warps x 16 rows. KV tiles of 64 keys, cp.async dbl-buf.
// grid (T/128, H, B), 256 threads.
// smem: Qh/Ql [128][72bf16] + 2 x (Kh,Kl,Vh,Vl [64][72bf16])
// ---------------------------------------------------------------------------
#define RS 144                         // smem row stride bytes (128B data + 16 pad)
#define QTILE_B (128*RS)               // 18432
#define KVTILE_B (64*RS)               // 9216
#define KVBUF_B (4*KVTILE_B)           // 36864
#define FL_SMEM (2*QTILE_B + 2*KVBUF_B) // 110592

__global__ __launch_bounds__(256, 1)
void flash3(const __nv_bfloat16* __restrict__ Qh, const __nv_bfloat16* __restrict__ Ql,
            const __nv_bfloat16* __restrict__ Kh, const __nv_bfloat16* __restrict__ Kl,
            const __nv_bfloat16* __restrict__ Vh, const __nv_bfloat16* __restrict__ Vl,
            __nv_bfloat16* __restrict__ Oh, __nv_bfloat16* __restrict__ Ol)
{
    extern __shared__ char sm[];
    const uint32_t sb = s2u(sm);
    const uint32_t kvb = sb + 2 * QTILE_B;

    const int tid = threadIdx.x;
    const int lane = tid & 31;
    const int wid = tid >> 5;
    const int qt = blockIdx.x;
    const int h  = blockIdx.y;
    const int b  = blockIdx.z;
    const size_t head = ((size_t)b * HH + h) * TT * HD;

    // ---- issue Q tiles (hi, lo) ----
#pragma unroll
    for (int i = 0; i < 8; i++) {
        const int idx = i * 256 + tid;           // 0..2047
        const int tile = idx >> 10;              // 0..1
        const int row = (idx >> 3) & 127;
        const int seg = idx & 7;
        const __nv_bfloat16* src = (tile == 0) ? Qh : Ql;
        cpa16(sb + tile * QTILE_B + row * RS + seg * 16,
              src + head + (size_t)(qt * 128 + row) * HD + seg * 8);
    }
    CP_COMMIT();

    auto issue_kv = [&](int t) {
        const int kv0 = t * 64;
        const uint32_t bu = kvb + (t & 1) * KVBUF_B;
#pragma unroll
        for (int i = 0; i < 8; i++) {
            const int idx = i * 256 + tid;       // 0..2047
            const int tile = idx >> 9;           // 0..3
            const int row = (idx >> 3) & 63;
            const int seg = idx & 7;
            const __nv_bfloat16* src = (tile == 0) ? Kh : (tile == 1) ? Kl
                                      : (tile == 2) ? Vh : Vl;
            cpa16(bu + tile * KVTILE_B + row * RS + seg * 16,
                  src + head + (size_t)(kv0 + row) * HD + seg * 8);
        }
        CP_COMMIT();
    };

    const int ntiles = (qt + 1) * 2;
    issue_kv(0);

    // ---- wait Q, extract Q fragments to registers ----
    CP_WAIT(1);
    __syncthreads();

    uint32_t qhf[4][4], qlf[4][4];
    {
        const uint32_t qaddr = sb + (uint32_t)((wid * 16 + (lane & 15)) * RS
                                               + (lane >> 4) * 16);
#pragma unroll
        for (int ck = 0; ck < 4; ck++) {
            ldsm_x4(qhf[ck], qaddr + ck * 32);
            ldsm_x4(qlf[ck], qaddr + QTILE_B + ck * 32);
        }
    }

    float m0 = -1e30f, m1 = -1e30f, l0 = 0.f, l1 = 0.f;
    float oacc[8][4];
#pragma unroll
    for (int nt = 0; nt < 8; nt++)
#pragma unroll
        for (int e = 0; e < 4; e++) oacc[nt][e] = 0.f;

    const int qrow = qt * 128 + wid * 16 + (lane >> 2);

    for (int t = 0; t < ntiles; t++) {
        if (t + 1 < ntiles) { issue_kv(t + 1); CP_WAIT(1); }
        else                { CP_WAIT(0); }
        __syncthreads();

        const uint32_t bu = kvb + (t & 1) * KVBUF_B;

        // ---- S = Q@K^T (3-pass split) ----
        float sacc[8][4];
#pragma unroll
        for (int nt = 0; nt < 8; nt++)
#pragma unroll
            for (int e = 0; e < 4; e++) sacc[nt][e] = 0.f;

#pragma unroll
        for (int nt = 0; nt < 8; nt++) {
            const uint32_t ka = bu + (uint32_t)((nt * 8 + (lane & 7)) * RS
                                                + (lane >> 3) * 16);
            uint32_t khf[8], klf[8];
            ldsm_x4(khf, ka);       ldsm_x4(khf + 4, ka + 64);
            ldsm_x4(klf, ka + KVTILE_B); ldsm_x4(klf + 4, ka + KVTILE_B + 64);
#pragma unroll
            for (int ck = 0; ck < 4; ck++) {
                mma16816(sacc[nt], qhf[ck], &khf[ck * 2]);
                mma16816(sacc[nt], qhf[ck], &klf[ck * 2]);
                mma16816(sacc[nt], qlf[ck], &khf[ck * 2]);
            }
        }

        // ---- causal mask (last two tiles) ----
        if (t >= ntiles - 2) {
            const int kv0 = t * 64;
#pragma unroll
            for (int nt = 0; nt < 8; nt++)
#pragma unroll
                for (int e = 0; e < 4; e++) {
                    const int key = kv0 + nt * 8 + 2 * (lane & 3) + (e & 1);
                    const int row = qrow + ((e & 2) ? 8 : 0);
                    if (key > row) sacc[nt][e] = -1e30f;
                }
        }

        // ---- online softmax (rows r and r+8) ----
#pragma unroll
        for (int hh = 0; hh < 2; hh++) {
            float& mprev = hh ? m1 : m0;
            float& lsum  = hh ? l1 : l0;
            float mx = -1e30f;
#pragma unroll
            for (int nt = 0; nt < 8; nt++)
                mx = fmaxf(mx, fmaxf(sacc[nt][hh*2], sacc[nt][hh*2+1]));
            mx = fmaxf(mx, __shfl_xor_sync(0xffffffffu, mx, 1));
            mx = fmaxf(mx, __shfl_xor_sync(0xffffffffu, mx, 2));
            const float mn = fmaxf(mprev, mx);
            const float alpha = __expf(mprev - mn);
            mprev = mn;
            float ps = 0.f;
#pragma unroll
            for (int nt = 0; nt < 8; nt++) {
                const float p0 = __expf(sacc[nt][hh*2]   - mn);
                const float p1 = __expf(sacc[nt][hh*2+1] - mn);
                ps += p0 + p1;
                sacc[nt][hh*2]   = p0;
                sacc[nt][hh*2+1] = p1;
                oacc[nt][hh*2]   *= alpha;
                oacc[nt][hh*2+1] *= alpha;
            }
            lsum = lsum * alpha + ps;
        }

        // ---- repack P (split hi/lo) into A fragments ----
        uint32_t aph[4][4], apl[4][4];
#pragma unroll
        for (int ck = 0; ck < 4; ck++) {
            splitpack(sacc[2*ck][0],   sacc[2*ck][1],   aph[ck][0], apl[ck][0]);
            splitpack(sacc[2*ck][2],   sacc[2*ck][3],   aph[ck][1], apl[ck][1]);
            splitpack(sacc[2*ck+1][0], sacc[2*ck+1][1], aph[ck][2], apl[ck][2]);
            splitpack(sacc[2*ck+1][2], sacc[2*ck+1][3], aph[ck][3], apl[ck][3]);
        }

        // ---- O += P@V (3-pass split), V via ldmatrix.trans ----
#pragma unroll
        for (int nt = 0; nt < 8; nt++) {
            const uint32_t va = bu + 2 * KVTILE_B + (uint32_t)(lane * RS + nt * 16);
            uint32_t vhf[8], vlf[8];
            ldsm_x4t(vhf, va);            ldsm_x4t(vhf + 4, va + 32 * RS);
            ldsm_x4t(vlf, va + KVTILE_B); ldsm_x4t(vlf + 4, va + KVTILE_B + 32 * RS);
#pragma unroll
            for (int ck = 0; ck < 4; ck++) {
                mma16816(oacc[nt], aph[ck], &vhf[ck * 2]);
                mma16816(oacc[nt], aph[ck], &vlf[ck * 2]);
                mma16816(oacc[nt], apl[ck], &vhf[ck * 2]);
            }
        }
        __syncthreads();
    }

    // ---- finalize: reduce l across quad, normalize, split-store ----
    l0 += __shfl_xor_sync(0xffffffffu, l0, 1);
    l0 += __shfl_xor_sync(0xffffffffu, l0, 2);
    l1 += __shfl_xor_sync(0xffffffffu, l1, 1);
    l1 += __shfl_xor_sync(0xffffffffu, l1, 2);
    const float inv0 = 1.f / l0;
    const float inv1 = 1.f / l1;

#pragma unroll
    for (int nt = 0; nt < 8; nt++) {
        const int d = nt * 8 + 2 * (lane & 3);
#pragma unroll
        for (int hh = 0; hh < 2; hh++) {
            const int row = qrow + hh * 8;                  // global t index
            const float inv = hh ? inv1 : inv0;
            const float v0 = oacc[nt][hh*2]   * inv;
            const float v1 = oacc[nt][hh*2+1] * inv;
            uint32_t hw, lw;
            splitpack(v0, v1, hw, lw);
            const size_t dst = ((size_t)(b * TT + row)) * CC + h * HD + d;
            *(uint32_t*)(g_aoh + dst) = hw;
            *(uint32_t*)(g_aol + dst) = lw;
        }
    }
}

// ---------------------------------------------------------------------------
extern "C" void kernel_launch(void* const* d_in, const int* in_sizes, int n_in,
                              void* d_out, int out_size)
{
    const float* x  = (const float*)d_in[0];
    const float* Wq = (const float*)d_in[1];
    const float* bq = (const float*)d_in[2];
    const float* Wk = (const float*)d_in[3];
    const float* bk = (const float*)d_in[4];
    const float* Wv = (const float*)d_in[5];
    const float* bv = (const float*)d_in[6];
    const float* Wo = (const float*)d_in[7];
    const float* bo = (const float*)d_in[8];
    float* out = (float*)d_out;

    __nv_bfloat16 *xh, *xl, *qh, *ql, *kh, *kl, *vh, *vl, *aoh, *aol, *wt;
    cudaGetSymbolAddress((void**)&xh,  g_xh);
    cudaGetSymbolAddress((void**)&xl,  g_xl);
    cudaGetSymbolAddress((void**)&qh,  g_qh);
    cudaGetSymbolAddress((void**)&ql,  g_ql);
    cudaGetSymbolAddress((void**)&kh,  g_kh);
    cudaGetSymbolAddress((void**)&kl,  g_kl);
    cudaGetSymbolAddress((void**)&vh,  g_vh);
    cudaGetSymbolAddress((void**)&vl,  g_vl);
    cudaGetSymbolAddress((void**)&aoh, g_aoh);
    cudaGetSymbolAddress((void**)&aol, g_aol);
    cudaGetSymbolAddress((void**)&wt,  g_wt);

    static bool attr_set = false;
    if (!attr_set) {
        cudaFuncSetAttribute(mmagemm<0>, cudaFuncAttributeMaxDynamicSharedMemorySize, GEMM_SMEM);
        cudaFuncSetAttribute(mmagemm<1>, cudaFuncAttributeMaxDynamicSharedMemorySize, GEMM_SMEM);
        cudaFuncSetAttribute(flash3, cudaFuncAttributeMaxDynamicSharedMemorySize, FL_SMEM);
        attr_set = true;
    }

    const int n4 = MROWS * CC / 4;
    splitx<<<n4 / 256, 256>>>(x, xh, xl);

    dim3 wgrid(CC / 32, CC / 32);
    wsplit<<<wgrid, 256>>>(Wq, wt + 0*CC*CC, wt + 1*CC*CC);
    wsplit<<<wgrid, 256>>>(Wk, wt + 2*CC*CC, wt + 3*CC*CC);
    wsplit<<<wgrid, 256>>>(Wv, wt + 4*CC*CC, wt + 5*CC*CC);
    wsplit<<<wgrid, 256>>>(Wo, wt + 6*CC*CC, wt + 7*CC*CC);

    dim3 ggrid(CC / 128, MROWS / 128);
    mmagemm<1><<<ggrid, 256, GEMM_SMEM>>>(xh, xl, wt + 0*CC*CC, wt + 1*CC*CC, bq,
                                          nullptr, qh, ql, 0.125f);
    mmagemm<1><<<ggrid, 256, GEMM_SMEM>>>(xh, xl, wt + 2*CC*CC, wt + 3*CC*CC, bk,
                                          nullptr, kh, kl, 1.0f);
    mmagemm<1><<<ggrid, 256, GEMM_SMEM>>>(xh, xl, wt + 4*CC*CC, wt + 5*CC*CC, bv,
                                          nullptr, vh, vl, 1.0f);

    dim3 att_grid(TT / 128, HH, BB);
    flash3<<<att_grid, 256, FL_SMEM>>>(qh, ql, kh, kl, vh, vl, aoh, aol);

    mmagemm<0><<<ggrid, 256, GEMM_SMEM>>>(aoh, aol, wt + 6*CC*CC, wt + 7*CC*CC, bo,
                                          out, nullptr, nullptr, 1.0f);
}

// round 7
// speedup vs baseline: 3.0213x; 1.0113x over previous
#include <cuda_runtime.h>
#include <cuda_bf16.h>
#include <stdint.h>
#include <math.h>

// Problem constants
#define BB 2
#define TT 2048
#define CC 1024
#define HH 16
#define HD 64
#define MROWS (BB*TT)

// ---------------------------------------------------------------------------
// Scratch (allocation-free rule: __device__ globals)
// ---------------------------------------------------------------------------
__device__ __nv_bfloat16 g_xh  [MROWS*CC];
__device__ __nv_bfloat16 g_xl  [MROWS*CC];
__device__ __nv_bfloat16 g_qkvh[3*MROWS*CC];   // [q|k|v][B,H,T,HD]
__device__ __nv_bfloat16 g_qkvl[3*MROWS*CC];
__device__ __nv_bfloat16 g_aoh [MROWS*CC];
__device__ __nv_bfloat16 g_aol [MROWS*CC];
__device__ __nv_bfloat16 g_wt  [8*CC*CC];      // [w*2+{hi,lo}][n][k]  (W^T, K-major)

// ---------------------------------------------------------------------------
// Warp-MMA helpers (base sm_80+ features)
// ---------------------------------------------------------------------------
__device__ __forceinline__ uint32_t s2u(const void* p) {
    uint32_t a;
    asm("{ .reg .u64 t; cvta.to.shared.u64 t, %1; cvt.u32.u64 %0, t; }"
        : "=r"(a) : "l"(p));
    return a;
}
__device__ __forceinline__ void ldsm_x4(uint32_t* r, uint32_t addr) {
    asm volatile("ldmatrix.sync.aligned.m8n8.x4.shared.b16 {%0,%1,%2,%3}, [%4];"
        : "=r"(r[0]), "=r"(r[1]), "=r"(r[2]), "=r"(r[3]) : "r"(addr));
}
__device__ __forceinline__ void ldsm_x4t(uint32_t* r, uint32_t addr) {
    asm volatile("ldmatrix.sync.aligned.m8n8.x4.trans.shared.b16 {%0,%1,%2,%3}, [%4];"
        : "=r"(r[0]), "=r"(r[1]), "=r"(r[2]), "=r"(r[3]) : "r"(addr));
}
__device__ __forceinline__ void mma16816(float* c, const uint32_t* a, const uint32_t* b) {
    asm volatile(
        "mma.sync.aligned.m16n8k16.row.col.f32.bf16.bf16.f32 "
        "{%0,%1,%2,%3}, {%4,%5,%6,%7}, {%8,%9}, {%0,%1,%2,%3};"
        : "+f"(c[0]), "+f"(c[1]), "+f"(c[2]), "+f"(c[3])
        : "r"(a[0]), "r"(a[1]), "r"(a[2]), "r"(a[3]), "r"(b[0]), "r"(b[1]));
}
__device__ __forceinline__ void cpa16(uint32_t dst, const void* src) {
    asm volatile("cp.async.ca.shared.global [%0], [%1], 16;" :: "r"(dst), "l"(src));
}
#define CP_COMMIT() asm volatile("cp.async.commit_group;" ::: "memory")
#define CP_WAIT(n)  asm volatile("cp.async.wait_group %0;" :: "n"(n) : "memory")

__device__ __forceinline__ void split1(float v, __nv_bfloat16& h, __nv_bfloat16& l) {
    h = __float2bfloat16_rn(v);
    l = __float2bfloat16_rn(v - __bfloat162float(h));
}
__device__ __forceinline__ uint32_t pk2(__nv_bfloat16 a, __nv_bfloat16 b) {
    return (uint32_t)__bfloat16_as_ushort(a) | ((uint32_t)__bfloat16_as_ushort(b) << 16);
}
__device__ __forceinline__ void splitpack(float a, float b, uint32_t& hi, uint32_t& lo) {
    __nv_bfloat16 ah, al, bh, bl;
    split1(a, ah, al); split1(b, bh, bl);
    hi = pk2(ah, bh); lo = pk2(al, bl);
}

// ---------------------------------------------------------------------------
// Prep kernels
// ---------------------------------------------------------------------------
__global__ void splitx(const float* __restrict__ x,
                       __nv_bfloat16* __restrict__ hi, __nv_bfloat16* __restrict__ lo)
{
    const int i = blockIdx.x * blockDim.x + threadIdx.x;
    float4 v = ((const float4*)x)[i];
    __nv_bfloat16 h0,h1,h2,h3,l0,l1,l2,l3;
    split1(v.x,h0,l0); split1(v.y,h1,l1); split1(v.z,h2,l2); split1(v.w,h3,l3);
    uint2 hw = { pk2(h0,h1), pk2(h2,h3) };
    uint2 lw = { pk2(l0,l1), pk2(l2,l3) };
    ((uint2*)hi)[i] = hw;
    ((uint2*)lo)[i] = lw;
}

// all 4 weight transposes+splits in one launch (z picks the weight)
__global__ __launch_bounds__(256)
void wsplit4(const float* __restrict__ W0, const float* __restrict__ W1,
             const float* __restrict__ W2, const float* __restrict__ W3,
             __nv_bfloat16* __restrict__ wt)
{
    __shared__ float t[32][33];
    const int wsel = blockIdx.z;
    const float* W = (wsel == 0) ? W0 : (wsel == 1) ? W1 : (wsel == 2) ? W2 : W3;
    __nv_bfloat16* th = wt + (size_t)(2 * wsel)     * CC * CC;
    __nv_bfloat16* tl = wt + (size_t)(2 * wsel + 1) * CC * CC;

    const int n0 = blockIdx.x * 32;
    const int k0 = blockIdx.y * 32;
    const int tx = threadIdx.x & 31;
    const int ty = threadIdx.x >> 5;
#pragma unroll
    for (int r = 0; r < 4; r++) {
        const int row = ty + r * 8;
        t[row][tx] = W[(size_t)(k0 + row) * CC + n0 + tx];
    }
    __syncthreads();
#pragma unroll
    for (int r = 0; r < 4; r++) {
        const int row = ty + r * 8;
        const float v = t[tx][row];
        __nv_bfloat16 h, l;
        split1(v, h, l);
        th[(size_t)(n0 + row) * CC + k0 + tx] = h;
        tl[(size_t)(n0 + row) * CC + k0 + tx] = l;
    }
}

// ---------------------------------------------------------------------------
// mma.sync split-bf16 GEMM, 4-stage cp.async pipeline, single sync per chunk.
// MODE 1 (fused QKV): B spans 3 weights (N=3072), bf16 hi/lo permuted out.
// MODE 0 (out proj):  N=1024, fp32 out.
// CTA 128x128, 8 warps (2m x 4n), K chunks of 16.
// ---------------------------------------------------------------------------
#define KC 16
#define TSTRIDE 48
#define TILE_B (128*TSTRIDE)
#define BUF_B  (4*TILE_B)            // 24576
#define GEMM_SMEM (4*BUF_B)          // 98304

template<int MODE>
__global__ __launch_bounds__(256, 2)
void mmagemm(const __nv_bfloat16* __restrict__ Ah, const __nv_bfloat16* __restrict__ Al,
             const __nv_bfloat16* __restrict__ Wt,     // g_wt base (MODE1) or [n][k] pair base (MODE0)
             const float* __restrict__ b0, const float* __restrict__ b1,
             const float* __restrict__ b2,
             float* __restrict__ Y,
             __nv_bfloat16* __restrict__ Yh, __nv_bfloat16* __restrict__ Yl)
{
    extern __shared__ char dsm[];
    const uint32_t sb = s2u(dsm);

    const int tid = threadIdx.x;
    const int lane = tid & 31;
    const int wid = tid >> 5;
    const int warp_m = wid & 1;
    const int warp_n = wid >> 1;
    const int bm = blockIdx.y * 128;
    const int bn = blockIdx.x * 128;

    // which weight (MODE1: 0..2), row within that weight's W^T
    const int which = (MODE == 1) ? (bn >> 10) : 0;
    const int nw = bn & (CC - 1);
    const __nv_bfloat16* Bh = Wt + (size_t)(2 * which)     * CC * CC;
    const __nv_bfloat16* Bl = Wt + (size_t)(2 * which + 1) * CC * CC;
    const float* bias = (MODE == 0) ? b0 : (which == 0) ? b0 : (which == 1) ? b1 : b2;
    const float scale = (MODE == 1 && which == 0) ? 0.125f : 1.0f;

    float acc[4][4][4];
#pragma unroll
    for (int i = 0; i < 4; i++)
#pragma unroll
        for (int j = 0; j < 4; j++)
#pragma unroll
            for (int q = 0; q < 4; q++) acc[i][j][q] = 0.f;

    auto issue = [&](int c) {
        const int k0 = c * KC;
        const uint32_t bu = sb + (c & 3) * BUF_B;
#pragma unroll
        for (int i = 0; i < 4; i++) {
            const int j = i * 256 + tid;
            const int row = (j >> 1) & 127;
            const int seg = j & 1;
            const __nv_bfloat16* s = (i == 0) ? Ah : (i == 1) ? Al : (i == 2) ? Bh : Bl;
            const int rb = (i < 2) ? bm : nw;
            cpa16(bu + i * TILE_B + row * TSTRIDE + seg * 16,
                  s + (size_t)(rb + row) * CC + k0 + seg * 8);
        }
        CP_COMMIT();
    };

    issue(0); issue(1); issue(2);

    const uint32_t a_off = (uint32_t)((warp_m * 64 + (lane & 15)) * TSTRIDE
                                      + (lane >> 4) * 16);
    const uint32_t b_off = (uint32_t)((warp_n * 32 + ((lane >> 4) * 8) + (lane & 7)) * TSTRIDE
                                      + ((lane >> 3) & 1) * 16);

    for (int c = 0; c < 64; c++) {
        CP_WAIT(2);
        __syncthreads();
        if (c + 3 < 64) issue(c + 3);

        const uint32_t bu = sb + (c & 3) * BUF_B;
        uint32_t af[4][4];
        uint32_t bhf[2][4], blf[2][4];

#pragma unroll
        for (int p = 0; p < 2; p++) {
            ldsm_x4(bhf[p], bu + 2*TILE_B + b_off + (uint32_t)(p * 16 * TSTRIDE));
            ldsm_x4(blf[p], bu + 3*TILE_B + b_off + (uint32_t)(p * 16 * TSTRIDE));
        }
#pragma unroll
        for (int mt = 0; mt < 4; mt++)
            ldsm_x4(af[mt], bu + a_off + (uint32_t)(mt * 16 * TSTRIDE));   // Ah
#pragma unroll
        for (int mt = 0; mt < 4; mt++)
#pragma unroll
            for (int nt = 0; nt < 4; nt++)
                mma16816(acc[mt][nt], af[mt], &bhf[nt >> 1][(nt & 1) * 2]);
#pragma unroll
        for (int mt = 0; mt < 4; mt++)
#pragma unroll
            for (int nt = 0; nt < 4; nt++)
                mma16816(acc[mt][nt], af[mt], &blf[nt >> 1][(nt & 1) * 2]);
#pragma unroll
        for (int mt = 0; mt < 4; mt++)
            ldsm_x4(af[mt], bu + TILE_B + a_off + (uint32_t)(mt * 16 * TSTRIDE)); // Al
#pragma unroll
        for (int mt = 0; mt < 4; mt++)
#pragma unroll
            for (int nt = 0; nt < 4; nt++)
                mma16816(acc[mt][nt], af[mt], &bhf[nt >> 1][(nt & 1) * 2]);
    }

#pragma unroll
    for (int mt = 0; mt < 4; mt++) {
#pragma unroll
        for (int nt = 0; nt < 4; nt++) {
            const int m0 = bm + warp_m * 64 + mt * 16 + (lane >> 2);
            const int nn = (nw) + warp_n * 32 + nt * 8 + 2 * (lane & 3); // col in [0,1024)
            const float bb0 = __ldg(bias + nn);
            const float bb1 = __ldg(bias + nn + 1);
#pragma unroll
            for (int half = 0; half < 2; half++) {
                const int m = m0 + half * 8;
                const int bb = m >> 11;
                const int tt = m & (TT - 1);
                const float v0 = (acc[mt][nt][half * 2 + 0] + bb0) * scale;
                const float v1 = (acc[mt][nt][half * 2 + 1] + bb1) * scale;
                if (MODE == 0) {
                    float2 r; r.x = v0; r.y = v1;
                    *(float2*)(Y + (size_t)m * CC + nn) = r;
                } else {
                    const int h = nn >> 6;
                    const int d = nn & (HD - 1);
                    const size_t dst = (size_t)which * MROWS * CC
                                     + (((size_t)bb * HH + h) * TT + tt) * HD + d;
                    uint32_t hw, lw;
                    splitpack(v0, v1, hw, lw);
                    *(uint32_t*)(Yh + dst) = hw;
                    *(uint32_t*)(Yl + dst) = lw;
                }
            }
        }
    }
}

// ---------------------------------------------------------------------------
// flash3: FA2-style mma.sync causal attention, split-bf16, 3-stage KV pipeline.
// CTA: 128 q-rows, 8 warps x 16 rows. KV tiles of 64 keys. 256 threads.
// ---------------------------------------------------------------------------
#define RS 144
#define QTILE_B (128*RS)                 // 18432
#define KVTILE_B (64*RS)                 // 9216
#define KVBUF_B (4*KVTILE_B)             // 36864
#define FL_SMEM (2*QTILE_B + 3*KVBUF_B)  // 147456

__global__ __launch_bounds__(256, 1)
void flash3(const __nv_bfloat16* __restrict__ Qh, const __nv_bfloat16* __restrict__ Ql,
            const __nv_bfloat16* __restrict__ Kh, const __nv_bfloat16* __restrict__ Kl,
            const __nv_bfloat16* __restrict__ Vh, const __nv_bfloat16* __restrict__ Vl)
{
    extern __shared__ char sm[];
    const uint32_t sb = s2u(sm);
    const uint32_t kvb = sb + 2 * QTILE_B;

    const int tid = threadIdx.x;
    const int lane = tid & 31;
    const int wid = tid >> 5;
    const int qt = blockIdx.x;
    const int h  = blockIdx.y;
    const int b  = blockIdx.z;
    const size_t head = ((size_t)b * HH + h) * TT * HD;

    // ---- issue Q tiles (hi, lo) ----
#pragma unroll
    for (int i = 0; i < 8; i++) {
        const int idx = i * 256 + tid;
        const int tile = idx >> 10;
        const int row = (idx >> 3) & 127;
        const int seg = idx & 7;
        const __nv_bfloat16* src = (tile == 0) ? Qh : Ql;
        cpa16(sb + tile * QTILE_B + row * RS + seg * 16,
              src + head + (size_t)(qt * 128 + row) * HD + seg * 8);
    }
    CP_COMMIT();

    auto issue_kv = [&](int t) {
        const int kv0 = t * 64;
        const uint32_t bu = kvb + (t % 3) * KVBUF_B;
#pragma unroll
        for (int i = 0; i < 8; i++) {
            const int idx = i * 256 + tid;
            const int tile = idx >> 9;
            const int row = (idx >> 3) & 63;
            const int seg = idx & 7;
            const __nv_bfloat16* src = (tile == 0) ? Kh : (tile == 1) ? Kl
                                      : (tile == 2) ? Vh : Vl;
            cpa16(bu + tile * KVTILE_B + row * RS + seg * 16,
                  src + head + (size_t)(kv0 + row) * HD + seg * 8);
        }
        CP_COMMIT();
    };

    const int ntiles = (qt + 1) * 2;
    issue_kv(0);
    if (1 < ntiles) issue_kv(1);

    // ---- wait Q, extract Q fragments ----
    CP_WAIT(2);
    __syncthreads();

    uint32_t qhf[4][4], qlf[4][4];
    {
        const uint32_t qaddr = sb + (uint32_t)((wid * 16 + (lane & 15)) * RS
                                               + (lane >> 4) * 16);
#pragma unroll
        for (int ck = 0; ck < 4; ck++) {
            ldsm_x4(qhf[ck], qaddr + ck * 32);
            ldsm_x4(qlf[ck], qaddr + QTILE_B + ck * 32);
        }
    }

    float m0 = -1e30f, m1 = -1e30f, l0 = 0.f, l1 = 0.f;
    float oacc[8][4];
#pragma unroll
    for (int nt = 0; nt < 8; nt++)
#pragma unroll
        for (int e = 0; e < 4; e++) oacc[nt][e] = 0.f;

    const int qrow = qt * 128 + wid * 16 + (lane >> 2);

    for (int t = 0; t < ntiles; t++) {
        if (t + 1 < ntiles) CP_WAIT(1);
        else                CP_WAIT(0);
        __syncthreads();
        if (t + 2 < ntiles) issue_kv(t + 2);

        const uint32_t bu = kvb + (t % 3) * KVBUF_B;

        // ---- S = Q@K^T (3-pass split) ----
        float sacc[8][4];
#pragma unroll
        for (int nt = 0; nt < 8; nt++)
#pragma unroll
            for (int e = 0; e < 4; e++) sacc[nt][e] = 0.f;

#pragma unroll
        for (int nt = 0; nt < 8; nt++) {
            const uint32_t ka = bu + (uint32_t)((nt * 8 + (lane & 7)) * RS
                                                + (lane >> 3) * 16);
            uint32_t khf[8], klf[8];
            ldsm_x4(khf, ka);            ldsm_x4(khf + 4, ka + 64);
            ldsm_x4(klf, ka + KVTILE_B); ldsm_x4(klf + 4, ka + KVTILE_B + 64);
#pragma unroll
            for (int ck = 0; ck < 4; ck++) {
                mma16816(sacc[nt], qhf[ck], &khf[ck * 2]);
                mma16816(sacc[nt], qhf[ck], &klf[ck * 2]);
                mma16816(sacc[nt], qlf[ck], &khf[ck * 2]);
            }
        }

        // ---- causal mask (last two tiles) ----
        if (t >= ntiles - 2) {
            const int kv0 = t * 64;
#pragma unroll
            for (int nt = 0; nt < 8; nt++)
#pragma unroll
                for (int e = 0; e < 4; e++) {
                    const int key = kv0 + nt * 8 + 2 * (lane & 3) + (e & 1);
                    const int row = qrow + ((e & 2) ? 8 : 0);
                    if (key > row) sacc[nt][e] = -1e30f;
                }
        }

        // ---- online softmax ----
#pragma unroll
        for (int hh = 0; hh < 2; hh++) {
            float& mprev = hh ? m1 : m0;
            float& lsum  = hh ? l1 : l0;
            float mx = -1e30f;
#pragma unroll
            for (int nt = 0; nt < 8; nt++)
                mx = fmaxf(mx, fmaxf(sacc[nt][hh*2], sacc[nt][hh*2+1]));
            mx = fmaxf(mx, __shfl_xor_sync(0xffffffffu, mx, 1));
            mx = fmaxf(mx, __shfl_xor_sync(0xffffffffu, mx, 2));
            const float mn = fmaxf(mprev, mx);
            const float alpha = __expf(mprev - mn);
            mprev = mn;
            float ps = 0.f;
#pragma unroll
            for (int nt = 0; nt < 8; nt++) {
                const float p0 = __expf(sacc[nt][hh*2]   - mn);
                const float p1 = __expf(sacc[nt][hh*2+1] - mn);
                ps += p0 + p1;
                sacc[nt][hh*2]   = p0;
                sacc[nt][hh*2+1] = p1;
                oacc[nt][hh*2]   *= alpha;
                oacc[nt][hh*2+1] *= alpha;
            }
            lsum = lsum * alpha + ps;
        }

        // ---- repack P (split hi/lo) into A fragments ----
        uint32_t aph[4][4], apl[4][4];
#pragma unroll
        for (int ck = 0; ck < 4; ck++) {
            splitpack(sacc[2*ck][0],   sacc[2*ck][1],   aph[ck][0], apl[ck][0]);
            splitpack(sacc[2*ck][2],   sacc[2*ck][3],   aph[ck][1], apl[ck][1]);
            splitpack(sacc[2*ck+1][0], sacc[2*ck+1][1], aph[ck][2], apl[ck][2]);
            splitpack(sacc[2*ck+1][2], sacc[2*ck+1][3], aph[ck][3], apl[ck][3]);
        }

        // ---- O += P@V (3-pass split) ----
#pragma unroll
        for (int nt = 0; nt < 8; nt++) {
            const uint32_t va = bu + 2 * KVTILE_B + (uint32_t)(lane * RS + nt * 16);
            uint32_t vhf[8], vlf[8];
            ldsm_x4t(vhf, va);            ldsm_x4t(vhf + 4, va + 32 * RS);
            ldsm_x4t(vlf, va + KVTILE_B); ldsm_x4t(vlf + 4, va + KVTILE_B + 32 * RS);
#pragma unroll
            for (int ck = 0; ck < 4; ck++) {
                mma16816(oacc[nt], aph[ck], &vhf[ck * 2]);
                mma16816(oacc[nt], aph[ck], &vlf[ck * 2]);
                mma16816(oacc[nt], apl[ck], &vhf[ck * 2]);
            }
        }
    }

    // ---- finalize ----
    l0 += __shfl_xor_sync(0xffffffffu, l0, 1);
    l0 += __shfl_xor_sync(0xffffffffu, l0, 2);
    l1 += __shfl_xor_sync(0xffffffffu, l1, 1);
    l1 += __shfl_xor_sync(0xffffffffu, l1, 2);
    const float inv0 = 1.f / l0;
    const float inv1 = 1.f / l1;

#pragma unroll
    for (int nt = 0; nt < 8; nt++) {
        const int d = nt * 8 + 2 * (lane & 3);
#pragma unroll
        for (int hh = 0; hh < 2; hh++) {
            const int row = qrow + hh * 8;
            const float inv = hh ? inv1 : inv0;
            const float v0 = oacc[nt][hh*2]   * inv;
            const float v1 = oacc[nt][hh*2+1] * inv;
            uint32_t hw, lw;
            splitpack(v0, v1, hw, lw);
            const size_t dst = ((size_t)(b * TT + row)) * CC + h * HD + d;
            *(uint32_t*)(g_aoh + dst) = hw;
            *(uint32_t*)(g_aol + dst) = lw;
        }
    }
}

// ---------------------------------------------------------------------------
extern "C" void kernel_launch(void* const* d_in, const int* in_sizes, int n_in,
                              void* d_out, int out_size)
{
    const float* x  = (const float*)d_in[0];
    const float* Wq = (const float*)d_in[1];
    const float* bq = (const float*)d_in[2];
    const float* Wk = (const float*)d_in[3];
    const float* bk = (const float*)d_in[4];
    const float* Wv = (const float*)d_in[5];
    const float* bv = (const float*)d_in[6];
    const float* Wo = (const float*)d_in[7];
    const float* bo = (const float*)d_in[8];
    float* out = (float*)d_out;

    __nv_bfloat16 *xh, *xl, *qkvh, *qkvl, *aoh, *aol, *wt;
    cudaGetSymbolAddress((void**)&xh,   g_xh);
    cudaGetSymbolAddress((void**)&xl,   g_xl);
    cudaGetSymbolAddress((void**)&qkvh, g_qkvh);
    cudaGetSymbolAddress((void**)&qkvl, g_qkvl);
    cudaGetSymbolAddress((void**)&aoh,  g_aoh);
    cudaGetSymbolAddress((void**)&aol,  g_aol);
    cudaGetSymbolAddress((void**)&wt,   g_wt);

    static bool attr_set = false;
    if (!attr_set) {
        cudaFuncSetAttribute(mmagemm<0>, cudaFuncAttributeMaxDynamicSharedMemorySize, GEMM_SMEM);
        cudaFuncSetAttribute(mmagemm<1>, cudaFuncAttributeMaxDynamicSharedMemorySize, GEMM_SMEM);
        cudaFuncSetAttribute(flash3, cudaFuncAttributeMaxDynamicSharedMemorySize, FL_SMEM);
        attr_set = true;
    }

    const int n4 = MROWS * CC / 4;
    splitx<<<n4 / 256, 256>>>(x, xh, xl);

    dim3 wgrid(CC / 32, CC / 32, 4);
    wsplit4<<<wgrid, 256>>>(Wq, Wk, Wv, Wo, wt);

    // fused QKV projection (N = 3072)
    dim3 qkv_grid(3 * CC / 128, MROWS / 128);   // (24, 32)
    mmagemm<1><<<qkv_grid, 256, GEMM_SMEM>>>(xh, xl, wt, bq, bk, bv,
                                             nullptr, qkvh, qkvl);

    dim3 att_grid(TT / 128, HH, BB);
    flash3<<<att_grid, 256, FL_SMEM>>>(qkvh, qkvl,
                                       qkvh + (size_t)MROWS*CC, qkvl + (size_t)MROWS*CC,
                                       qkvh + 2*(size_t)MROWS*CC, qkvl + 2*(size_t)MROWS*CC);

    // output projection (N = 1024)
    dim3 out_grid(CC / 128, MROWS / 128);       // (8, 32)
    mmagemm<0><<<out_grid, 256, GEMM_SMEM>>>(aoh, aol, wt + 6*(size_t)CC*CC,
                                             bo, nullptr, nullptr,
                                             out, nullptr, nullptr);
}